// round 6
// baseline (speedup 1.0000x reference)
#include <cuda_runtime.h>
#include <cuda_bf16.h>
#include <cstdint>

// Problem constants (fixed shapes)
#define PB    128        // batch
#define PT    196        // patches per view
#define P2T   392        // 2*T
#define PENC  1024       // encoder dim
#define PDEC  512        // decoder dim
#define PV    98         // visible tokens per row
#define PM    294        // masked tokens per row
#define MROWS (PB*PV)    // 12544 GEMM rows

// visible ids scratch
__device__ int g_vis[MROWS];

// ---------------------------------------------------------------------------
// Kernel 1: compute visible ids (sorted complement of masked_ids per row).
// Handles masked_ids delivered as either int64 or int32 (runtime detect).
// ---------------------------------------------------------------------------
__global__ void vis_ids_kernel(const void* __restrict__ mids_raw) {
    __shared__ unsigned char flags[P2T];
    __shared__ int is64;
    const int b   = blockIdx.x;
    const int tid = threadIdx.x;   // 128 threads

    if (tid == 0) {
        // Detect: if the first row's 294 values, read as int64, are all in
        // [0, 2T), the buffer is int64. Int32 payload reinterpreted as int64
        // produces huge values (hi word = next id, almost surely nonzero).
        const long long* p = (const long long*)mids_raw;
        int ok = 1;
        for (int i = 0; i < PM; i++) {
            long long v = p[i];
            if (v < 0 || v >= P2T) { ok = 0; break; }
        }
        is64 = ok;
    }
    for (int i = tid; i < P2T; i += 128) flags[i] = 1;
    __syncthreads();

    if (is64) {
        const long long* m = ((const long long*)mids_raw) + (size_t)b * PM;
        for (int i = tid; i < PM; i += 128) flags[(int)m[i]] = 0;
    } else {
        const int* m = ((const int*)mids_raw) + (size_t)b * PM;
        for (int i = tid; i < PM; i += 128) flags[m[i]] = 0;
    }
    __syncthreads();

    if (tid == 0) {
        int c = 0;
        #pragma unroll 4
        for (int t = 0; t < P2T; t++)
            if (flags[t]) g_vis[b * PV + (c++)] = t;
    }
}

// ---------------------------------------------------------------------------
// Kernel 2: base fill  out[b][t][d] = mask_token[d] + pos[t][d] + ve[t>=T][d]
// float4-vectorized, one element per thread (write-bandwidth bound).
// ---------------------------------------------------------------------------
__global__ void fill_base_kernel(const float4* __restrict__ mt4,
                                 const float4* __restrict__ pos4,
                                 const float*  __restrict__ ve,
                                 float4* __restrict__ out4) {
    const int i = blockIdx.x * blockDim.x + threadIdx.x;   // 0 .. 6422528
    if (i >= PB * P2T * (PDEC / 4)) return;
    const int d4 = i & 127;                 // DEC/4 = 128
    const int t  = (i >> 7) % P2T;
    const float4 m = mt4[d4];
    const float4 p = pos4[t * 128 + d4];
    const float4 v = ((const float4*)(ve + (t >= PT ? PDEC : 0)))[d4];
    out4[i] = make_float4(m.x + p.x + v.x, m.y + p.y + v.y,
                          m.z + p.z + v.z, m.w + p.w + v.w);
}

// ---------------------------------------------------------------------------
// Kernel 3: TF32 tensor-core GEMM (12544x512x1024) with fused scatter epilogue
//   out[b][vis[b][v]][n] = sum_k x[b][v][k]*W[n][k] + bias[n] + pos + ve
// BM=128, BN=128, BK=16, 256 threads (8 warps, 2x4), mma.sync m16n8k8 tf32.
// M=98*128 exact, N=4*128 exact, K=64*16 exact -> no bounds checks.
// ---------------------------------------------------------------------------
#define LDT 20   // padded shared row stride (floats): conflict-free frag loads

__device__ __forceinline__ void cp_async16(void* smem, const void* gmem) {
    uint32_t s = (uint32_t)__cvta_generic_to_shared(smem);
    asm volatile("cp.async.cg.shared.global [%0], [%1], 16;\n" :: "r"(s), "l"(gmem));
}
__device__ __forceinline__ void cp_commit() {
    asm volatile("cp.async.commit_group;\n" ::: "memory");
}
template<int N> __device__ __forceinline__ void cp_wait() {
    asm volatile("cp.async.wait_group %0;\n" :: "n"(N) : "memory");
}
__device__ __forceinline__ uint32_t f2tf(float f) {
    uint32_t u;
    asm("cvt.rna.tf32.f32 %0, %1;" : "=r"(u) : "f"(f));
    return u;
}
__device__ __forceinline__ void mma_tf32(float* c, const uint32_t* a, const uint32_t* b) {
    asm volatile(
        "mma.sync.aligned.m16n8k8.row.col.f32.tf32.tf32.f32 "
        "{%0,%1,%2,%3},{%4,%5,%6,%7},{%8,%9},{%0,%1,%2,%3};\n"
        : "+f"(c[0]), "+f"(c[1]), "+f"(c[2]), "+f"(c[3])
        : "r"(a[0]), "r"(a[1]), "r"(a[2]), "r"(a[3]), "r"(b[0]), "r"(b[1]));
}

__global__ __launch_bounds__(256)
void gemm_scatter_kernel(const float* __restrict__ x,
                         const float* __restrict__ W,
                         const float* __restrict__ bias,
                         const float* __restrict__ pos,
                         const float* __restrict__ ve,
                         float* __restrict__ out) {
    __shared__ float As[2][128 * LDT];
    __shared__ float Bs[2][128 * LDT];

    const int tid  = threadIdx.x;
    const int warp = tid >> 5;
    const int lane = tid & 31;
    const int g    = lane >> 2;    // group id (row within 8)
    const int tig  = lane & 3;     // thread in group (k / col pair)
    const int wm   = warp >> 2;    // 0..1
    const int wn   = warp & 3;     // 0..3
    const int bm0  = blockIdx.y * 128;
    const int bn0  = blockIdx.x * 128;

    // global->shared load assignment: 512 float4 per matrix tile, 2 per thread
    const int r0 = tid >> 2,          c0 = (tid & 3) * 4;          // float4 id tid
    const int r1 = (tid + 256) >> 2,  c1 = ((tid + 256) & 3) * 4;  // float4 id tid+256

    auto issue = [&](int kt, int buf) {
        const int k0 = kt * 16;
        cp_async16(&As[buf][r0 * LDT + c0], x + (size_t)(bm0 + r0) * PENC + k0 + c0);
        cp_async16(&As[buf][r1 * LDT + c1], x + (size_t)(bm0 + r1) * PENC + k0 + c1);
        cp_async16(&Bs[buf][r0 * LDT + c0], W + (size_t)(bn0 + r0) * PENC + k0 + c0);
        cp_async16(&Bs[buf][r1 * LDT + c1], W + (size_t)(bn0 + r1) * PENC + k0 + c1);
    };

    float acc[4][4][4];
    #pragma unroll
    for (int mi = 0; mi < 4; mi++)
        #pragma unroll
        for (int ni = 0; ni < 4; ni++)
            #pragma unroll
            for (int ci = 0; ci < 4; ci++) acc[mi][ni][ci] = 0.f;

    issue(0, 0);
    cp_commit();

    const int KT = PENC / 16;   // 64
    for (int kt = 0; kt < KT; kt++) {
        if (kt + 1 < KT) {
            issue(kt + 1, (kt + 1) & 1);
            cp_commit();
            cp_wait<1>();
        } else {
            cp_wait<0>();
        }
        __syncthreads();

        const float* A = As[kt & 1];
        const float* B = Bs[kt & 1];
        #pragma unroll
        for (int ks = 0; ks < 2; ks++) {
            const int kb = ks * 8;
            uint32_t af[4][4], bf[4][2];
            #pragma unroll
            for (int mi = 0; mi < 4; mi++) {
                const int ar = wm * 64 + mi * 16 + g;
                af[mi][0] = f2tf(A[(ar    ) * LDT + kb + tig    ]);
                af[mi][1] = f2tf(A[(ar + 8) * LDT + kb + tig    ]);
                af[mi][2] = f2tf(A[(ar    ) * LDT + kb + tig + 4]);
                af[mi][3] = f2tf(A[(ar + 8) * LDT + kb + tig + 4]);
            }
            #pragma unroll
            for (int ni = 0; ni < 4; ni++) {
                const int br = wn * 32 + ni * 8 + g;
                bf[ni][0] = f2tf(B[br * LDT + kb + tig    ]);
                bf[ni][1] = f2tf(B[br * LDT + kb + tig + 4]);
            }
            #pragma unroll
            for (int mi = 0; mi < 4; mi++)
                #pragma unroll
                for (int ni = 0; ni < 4; ni++)
                    mma_tf32(acc[mi][ni], af[mi], bf[ni]);
        }
        __syncthreads();
    }

    // -------- fused scatter epilogue --------
    #pragma unroll
    for (int mi = 0; mi < 4; mi++) {
        #pragma unroll
        for (int h = 0; h < 2; h++) {
            const int r  = bm0 + wm * 64 + mi * 16 + g + h * 8;   // GEMM row
            const int bb = r / PV;
            const int v  = r - bb * PV;
            const int t  = g_vis[bb * PV + v];
            const float* posrow = pos + (size_t)t * PDEC;
            const float* verow  = ve + (t >= PT ? PDEC : 0);
            float* outrow = out + ((size_t)bb * P2T + t) * PDEC;
            #pragma unroll
            for (int ni = 0; ni < 4; ni++) {
                const int n = bn0 + wn * 32 + ni * 8 + 2 * tig;
                float o0 = acc[mi][ni][2 * h + 0] + bias[n]     + posrow[n]     + verow[n];
                float o1 = acc[mi][ni][2 * h + 1] + bias[n + 1] + posrow[n + 1] + verow[n + 1];
                *(float2*)(outrow + n) = make_float2(o0, o1);
            }
        }
    }
}

// ---------------------------------------------------------------------------
// launch
// ---------------------------------------------------------------------------
extern "C" void kernel_launch(void* const* d_in, const int* in_sizes, int n_in,
                              void* d_out, int out_size) {
    const float* x    = (const float*)d_in[0];  // (B, V, ENC)
    const void*  mids = d_in[1];                // (B, M) int64 OR int32
    const float* W    = (const float*)d_in[2];  // (DEC, ENC)
    const float* bias = (const float*)d_in[3];  // (DEC)
    const float* mt   = (const float*)d_in[4];  // (1,1,DEC)
    const float* pos  = (const float*)d_in[5];  // (1, 2T, DEC)
    const float* ve   = (const float*)d_in[6];  // (2, DEC)
    float* out = (float*)d_out;                 // (B, 2T, DEC)

    int* vis_ptr;
    cudaGetSymbolAddress((void**)&vis_ptr, g_vis);

    // 1) visible ids
    vis_ids_kernel<<<PB, 128>>>(mids);

    // 2) base fill (entire output = mask_token + pos + view_embed)
    {
        const int total4 = PB * P2T * (PDEC / 4);      // 6,422,528
        const int threads = 256;
        const int blocks = (total4 + threads - 1) / threads;
        fill_base_kernel<<<blocks, threads>>>((const float4*)mt, (const float4*)pos,
                                              ve, (float4*)out);
    }

    // 3) TF32 GEMM + scatter of visible tokens (overwrites base at visible t)
    {
        dim3 grid(PDEC / 128, MROWS / 128);            // (4, 98)
        gemm_scatter_kernel<<<grid, 256>>>(x, W, bias, pos, ve, out);
    }
    (void)in_sizes; (void)n_in; (void)out_size; (void)vis_ptr;
}

// round 10
// speedup vs baseline: 1.4632x; 1.4632x over previous
#include <cuda_runtime.h>
#include <cuda_fp16.h>
#include <cuda_bf16.h>
#include <cstdint>

// ---------------- problem constants ----------------
#define PB    128
#define PT    196
#define P2T   392
#define PENC  1024
#define PDEC  512
#define PV    98
#define PM    294
#define MROWS (PB*PV)          // 12544

// ---------------- device scratch ----------------
__device__ int            g_vis[MROWS];
__device__ unsigned char  g_flags[PB * P2T];                       // 1 = visible
__device__ __align__(16) __half g_xh[(size_t)MROWS * PENC];        // 25.7 MB
__device__ __align__(16) __half g_wh[(size_t)PDEC  * PENC];        // 1 MB

// ===========================================================================
// Kernel 1: visible ids + visibility flags (parallel scan, parallel detect)
// ===========================================================================
__global__ void vis_ids_kernel(const void* __restrict__ mids_raw) {
    __shared__ unsigned char flags[512];
    __shared__ int warp_sum[4];
    __shared__ int is64s;
    const int b = blockIdx.x, tid = threadIdx.x;
    const int lane = tid & 31, wid = tid >> 5;

    if (tid == 0) is64s = 1;
    #pragma unroll
    for (int i = 0; i < 4; i++) {
        const int idx = tid + i * 128;
        flags[idx] = (idx < P2T) ? 1 : 0;          // FIX: 384..391 must be 1
    }
    __syncthreads();
    {   // int64 vs int32 detection on row 0 (racy 0-write is fine)
        const long long* p = (const long long*)mids_raw;
        for (int i = tid; i < PM; i += 128) {
            long long v = p[i];
            if (v < 0 || v >= P2T) is64s = 0;
        }
    }
    __syncthreads();
    if (is64s) {
        const long long* m = ((const long long*)mids_raw) + (size_t)b * PM;
        for (int i = tid; i < PM; i += 128) flags[(int)m[i]] = 0;
    } else {
        const int* m = ((const int*)mids_raw) + (size_t)b * PM;
        for (int i = tid; i < PM; i += 128) flags[m[i]] = 0;
    }
    __syncthreads();

    int f[4], local = 0;
    #pragma unroll
    for (int j = 0; j < 4; j++) { f[j] = flags[tid * 4 + j]; local += f[j]; }
    int s = local;
    #pragma unroll
    for (int off = 1; off < 32; off <<= 1) {
        int n = __shfl_up_sync(0xffffffffu, s, off);
        if (lane >= off) s += n;
    }
    if (lane == 31) warp_sum[wid] = s;
    __syncthreads();
    int base = 0;
    #pragma unroll
    for (int w = 0; w < 4; w++) if (w < wid) base += warp_sum[w];
    int c = base + s - local;
    #pragma unroll
    for (int j = 0; j < 4; j++) {
        int t = tid * 4 + j;
        if (f[j]) g_vis[b * PV + (c++)] = t;
    }
    for (int i = tid; i < P2T; i += 128) g_flags[b * P2T + i] = flags[i];
}

// ===========================================================================
// Kernel 2: fp32 -> fp16 conversion of x and W into scratch
// ===========================================================================
#define NX4 (MROWS * PENC / 4)       // 3,211,264
#define NW4 (PDEC * PENC / 4)        //   131,072
__global__ void convert_kernel(const float4* __restrict__ x4,
                               const float4* __restrict__ w4) {
    const int i = blockIdx.x * blockDim.x + threadIdx.x;
    float4 v; __half* dst;
    if (i < NX4)            { v = x4[i];        dst = g_xh + (size_t)i * 4; }
    else if (i < NX4 + NW4) { v = w4[i - NX4];  dst = g_wh + (size_t)(i - NX4) * 4; }
    else return;
    __half2 h0 = __floats2half2_rn(v.x, v.y);
    __half2 h1 = __floats2half2_rn(v.z, v.w);
    uint2 p; p.x = *(const uint32_t*)&h0; p.y = *(const uint32_t*)&h1;
    *(uint2*)dst = p;
}

// ===========================================================================
// Kernel 3: fill MASKED positions only: mask_token + pos + view_embed
// ===========================================================================
__global__ void fill_base_kernel(const float4* __restrict__ mt4,
                                 const float4* __restrict__ pos4,
                                 const float*  __restrict__ ve,
                                 float4* __restrict__ out4) {
    const int i = blockIdx.x * blockDim.x + threadIdx.x;
    if (i >= PB * P2T * (PDEC / 4)) return;
    const int bt = i >> 7;               // b*392 + t (warp-uniform)
    if (g_flags[bt]) return;             // visible -> GEMM writes it
    const int d4 = i & 127;
    const int t  = bt % P2T;
    const float4 m = mt4[d4];
    const float4 p = pos4[t * 128 + d4];
    const float4 v = ((const float4*)(ve + (t >= PT ? PDEC : 0)))[d4];
    out4[i] = make_float4(m.x + p.x + v.x, m.y + p.y + v.y,
                          m.z + p.z + v.z, m.w + p.w + v.w);
}

// ===========================================================================
// Kernel 4: fp16 mma.sync GEMM (12544 x 512 x 1024) + fused scatter epilogue
//   BM=128, BN=128, BK=64 (128B rows, SW128 swizzle, conflict-free ldmatrix)
//   256 threads = 8 warps (2m x 4n), warp tile 64x32, m16n8k16 HMMA.
// ===========================================================================
__device__ __forceinline__ void cp_async16(void* smem, const void* gmem) {
    uint32_t s = (uint32_t)__cvta_generic_to_shared(smem);
    asm volatile("cp.async.cg.shared.global [%0], [%1], 16;\n" :: "r"(s), "l"(gmem));
}
__device__ __forceinline__ void cp_commit() {
    asm volatile("cp.async.commit_group;\n" ::: "memory");
}
template<int N> __device__ __forceinline__ void cp_wait() {
    asm volatile("cp.async.wait_group %0;\n" :: "n"(N) : "memory");
}
__device__ __forceinline__ void ldsm_x4(uint32_t& r0, uint32_t& r1,
                                        uint32_t& r2, uint32_t& r3, uint32_t addr) {
    asm volatile("ldmatrix.sync.aligned.m8n8.x4.shared.b16 {%0,%1,%2,%3}, [%4];"
                 : "=r"(r0), "=r"(r1), "=r"(r2), "=r"(r3) : "r"(addr));
}
__device__ __forceinline__ void mma_f16(float* c, const uint32_t* a, const uint32_t* b) {
    asm volatile(
        "mma.sync.aligned.m16n8k16.row.col.f32.f16.f16.f32 "
        "{%0,%1,%2,%3},{%4,%5,%6,%7},{%8,%9},{%0,%1,%2,%3};\n"
        : "+f"(c[0]), "+f"(c[1]), "+f"(c[2]), "+f"(c[3])
        : "r"(a[0]), "r"(a[1]), "r"(a[2]), "r"(a[3]), "r"(b[0]), "r"(b[1]));
}
#define SWZ(off) ((off) ^ (((off) >> 3) & 0x70))   // SW128: XOR bits[6:4] with row&7

#define TILE_B   16384                     // 128 rows x 128 bytes
#define GEMM_SMEM (4 * TILE_B)             // A0,A1,B0,B1 = 64 KB

__global__ __launch_bounds__(256, 1)
void gemm_hmma_kernel(const float* __restrict__ bias,
                      const float* __restrict__ pos,
                      const float* __restrict__ ve,
                      float* __restrict__ out) {
    extern __shared__ char smem[];
    char* As = smem;                 // 2 stages x 16 KB
    char* Bs = smem + 2 * TILE_B;    // 2 stages x 16 KB

    const int tid  = threadIdx.x;
    const int warp = tid >> 5, lane = tid & 31;
    const int g    = lane >> 2;      // 0..7
    const int tig  = lane & 3;       // 0..3
    const int wm   = warp >> 2;      // 0..1
    const int wn   = warp & 3;       // 0..3
    const int bn0  = blockIdx.x * 128, bm0 = blockIdx.y * 128;

    // global->shared: 1024 16B units per tile, 4 per thread
    auto issue = [&](int kt, int buf) {
        const int kc0 = kt * 64;
        #pragma unroll
        for (int i = 0; i < 4; i++) {
            const int idx16 = tid + i * 256;
            const int row = idx16 >> 3, c16 = idx16 & 7;
            const int soff = SWZ(row * 128 + c16 * 16);
            cp_async16(As + buf * TILE_B + soff,
                       g_xh + (size_t)(bm0 + row) * PENC + kc0 + c16 * 8);
            cp_async16(Bs + buf * TILE_B + soff,
                       g_wh + (size_t)(bn0 + row) * PENC + kc0 + c16 * 8);
        }
    };

    float acc[4][4][4];
    #pragma unroll
    for (int mi = 0; mi < 4; mi++)
        #pragma unroll
        for (int ni = 0; ni < 4; ni++)
            #pragma unroll
            for (int ci = 0; ci < 4; ci++) acc[mi][ni][ci] = 0.f;

    // ldmatrix lane-address components (within-tile)
    const int a_row = (lane & 15);           // row offset within m16 tile
    const int a_chk = (lane >> 4);           // +0 / +1 k-chunk
    const int b_row = ((lane >> 4) * 8) + (lane & 7);   // row offset within n16 pair
    const int b_chk = ((lane >> 3) & 1);     // +0 / +1 k-chunk

    issue(0, 0);
    cp_commit();

    const int KT = PENC / 64;                // 16
    for (int kt = 0; kt < KT; kt++) {
        if (kt + 1 < KT) { issue(kt + 1, (kt + 1) & 1); cp_commit(); cp_wait<1>(); }
        else             { cp_wait<0>(); }
        __syncthreads();

        const uint32_t sA = (uint32_t)__cvta_generic_to_shared(As + (kt & 1) * TILE_B);
        const uint32_t sB = (uint32_t)__cvta_generic_to_shared(Bs + (kt & 1) * TILE_B);

        #pragma unroll
        for (int ks = 0; ks < 4; ks++) {     // k16 steps within BK=64
            uint32_t af[4][4], bf[4][2];
            #pragma unroll
            for (int mi = 0; mi < 4; mi++) {
                const int r = wm * 64 + mi * 16 + a_row;
                const int c = (ks * 2 + a_chk) ^ (r & 7);
                ldsm_x4(af[mi][0], af[mi][1], af[mi][2], af[mi][3],
                        sA + r * 128 + c * 16);
            }
            #pragma unroll
            for (int nj = 0; nj < 2; nj++) {
                const int r = wn * 32 + nj * 16 + b_row;
                const int c = (ks * 2 + b_chk) ^ (r & 7);
                ldsm_x4(bf[2*nj][0], bf[2*nj][1], bf[2*nj+1][0], bf[2*nj+1][1],
                        sB + r * 128 + c * 16);
            }
            #pragma unroll
            for (int mi = 0; mi < 4; mi++)
                #pragma unroll
                for (int ni = 0; ni < 4; ni++)
                    mma_f16(acc[mi][ni], af[mi], bf[ni]);
        }
        __syncthreads();
    }

    // -------- fused scatter epilogue --------
    #pragma unroll
    for (int mi = 0; mi < 4; mi++) {
        #pragma unroll
        for (int h = 0; h < 2; h++) {
            const int r  = bm0 + wm * 64 + mi * 16 + g + h * 8;   // GEMM row
            const int bb = r / PV;
            const int v  = r - bb * PV;
            const int t  = g_vis[bb * PV + v];
            const float* posrow = pos + (size_t)t * PDEC;
            const float* verow  = ve + (t >= PT ? PDEC : 0);
            float* outrow = out + ((size_t)bb * P2T + t) * PDEC;
            #pragma unroll
            for (int ni = 0; ni < 4; ni++) {
                const int n = bn0 + wn * 32 + ni * 8 + 2 * tig;
                float o0 = acc[mi][ni][2 * h + 0] + bias[n]     + posrow[n]     + verow[n];
                float o1 = acc[mi][ni][2 * h + 1] + bias[n + 1] + posrow[n + 1] + verow[n + 1];
                *(float2*)(outrow + n) = make_float2(o0, o1);
            }
        }
    }
}

// ===========================================================================
// launch
// ===========================================================================
extern "C" void kernel_launch(void* const* d_in, const int* in_sizes, int n_in,
                              void* d_out, int out_size) {
    const float* x    = (const float*)d_in[0];  // (B, V, ENC)
    const void*  mids = d_in[1];                // (B, M) int64 or int32
    const float* W    = (const float*)d_in[2];  // (DEC, ENC)
    const float* bias = (const float*)d_in[3];  // (DEC)
    const float* mt   = (const float*)d_in[4];  // (1,1,DEC)
    const float* pos  = (const float*)d_in[5];  // (1, 2T, DEC)
    const float* ve   = (const float*)d_in[6];  // (2, DEC)
    float* out = (float*)d_out;                 // (B, 2T, DEC)

    cudaFuncSetAttribute(gemm_hmma_kernel,
                         cudaFuncAttributeMaxDynamicSharedMemorySize, GEMM_SMEM);

    vis_ids_kernel<<<PB, 128>>>(mids);

    {   // fp32 -> fp16 scratch
        const int total = NX4 + NW4;
        convert_kernel<<<(total + 255) / 256, 256>>>((const float4*)x, (const float4*)W);
    }
    {   // masked-position fill
        const int total4 = PB * P2T * (PDEC / 4);
        fill_base_kernel<<<(total4 + 255) / 256, 256>>>((const float4*)mt,
                                                        (const float4*)pos, ve, (float4*)out);
    }
    {   // fp16 HMMA GEMM + scatter of visible tokens
        dim3 grid(PDEC / 128, MROWS / 128);             // (4, 98)
        gemm_hmma_kernel<<<grid, 256, GEMM_SMEM>>>(bias, pos, ve, out);
    }
    (void)in_sizes; (void)n_in; (void)out_size;
}

// round 13
// speedup vs baseline: 1.6624x; 1.1362x over previous
#include <cuda_runtime.h>
#include <cuda_fp16.h>
#include <cuda_bf16.h>
#include <cstdint>

// ---------------- problem constants ----------------
#define PB    128
#define PT    196
#define P2T   392
#define PENC  1024
#define PDEC  512
#define PV    98
#define PM    294
#define MROWS (PB*PV)          // 12544

// ---------------- device scratch ----------------
__device__ int            g_vis[MROWS];
__device__ unsigned char  g_flags[PB * P2T];                       // 1 = visible
__device__ __align__(16) __half g_xh[(size_t)MROWS * PENC];        // 25.7 MB
__device__ __align__(16) __half g_wh[(size_t)PDEC  * PENC];        // 1 MB

// ===========================================================================
// Kernel 1: visible ids + visibility flags (parallel scan, parallel detect)
// ===========================================================================
__global__ void vis_ids_kernel(const void* __restrict__ mids_raw) {
    __shared__ unsigned char flags[512];
    __shared__ int warp_sum[4];
    __shared__ int is64s;
    const int b = blockIdx.x, tid = threadIdx.x;
    const int lane = tid & 31, wid = tid >> 5;

    if (tid == 0) is64s = 1;
    #pragma unroll
    for (int i = 0; i < 4; i++) {
        const int idx = tid + i * 128;
        flags[idx] = (idx < P2T) ? 1 : 0;
    }
    __syncthreads();
    {   // int64 vs int32 detection on row 0 (racy 0-write is fine)
        const long long* p = (const long long*)mids_raw;
        for (int i = tid; i < PM; i += 128) {
            long long v = p[i];
            if (v < 0 || v >= P2T) is64s = 0;
        }
    }
    __syncthreads();
    if (is64s) {
        const long long* m = ((const long long*)mids_raw) + (size_t)b * PM;
        for (int i = tid; i < PM; i += 128) flags[(int)m[i]] = 0;
    } else {
        const int* m = ((const int*)mids_raw) + (size_t)b * PM;
        for (int i = tid; i < PM; i += 128) flags[m[i]] = 0;
    }
    __syncthreads();

    int f[4], local = 0;
    #pragma unroll
    for (int j = 0; j < 4; j++) { f[j] = flags[tid * 4 + j]; local += f[j]; }
    int s = local;
    #pragma unroll
    for (int off = 1; off < 32; off <<= 1) {
        int n = __shfl_up_sync(0xffffffffu, s, off);
        if (lane >= off) s += n;
    }
    if (lane == 31) warp_sum[wid] = s;
    __syncthreads();
    int base = 0;
    #pragma unroll
    for (int w = 0; w < 4; w++) if (w < wid) base += warp_sum[w];
    int c = base + s - local;
    #pragma unroll
    for (int j = 0; j < 4; j++) {
        int t = tid * 4 + j;
        if (f[j]) g_vis[b * PV + (c++)] = t;
    }
    for (int i = tid; i < P2T; i += 128) g_flags[b * P2T + i] = flags[i];
}

// ===========================================================================
// Kernel 2 (fused): fp32->fp16 convert of x and W  +  masked-position fill
//   range-split grid; all three parts are pure-bandwidth.
// ===========================================================================
#define NX4   (MROWS * PENC / 4)          // 3,211,264
#define NW4   (PDEC * PENC / 4)           //   131,072
#define NF4   (PB * P2T * (PDEC / 4))     // 6,422,528
#define NALL4 (NX4 + NW4 + NF4)

__global__ void prep_kernel(const float4* __restrict__ x4,
                            const float4* __restrict__ w4,
                            const float4* __restrict__ mt4,
                            const float4* __restrict__ pos4,
                            const float*  __restrict__ ve,
                            float4* __restrict__ out4) {
    const int i = blockIdx.x * blockDim.x + threadIdx.x;
    if (i < NX4 + NW4) {
        float4 v; __half* dst;
        if (i < NX4) { v = x4[i];       dst = g_xh + (size_t)i * 4; }
        else         { v = w4[i - NX4]; dst = g_wh + (size_t)(i - NX4) * 4; }
        __half2 h0 = __floats2half2_rn(v.x, v.y);
        __half2 h1 = __floats2half2_rn(v.z, v.w);
        uint2 p; p.x = *(const uint32_t*)&h0; p.y = *(const uint32_t*)&h1;
        *(uint2*)dst = p;
        return;
    }
    const int j = i - (NX4 + NW4);
    if (j >= NF4) return;
    const int bt = j >> 7;               // b*392 + t (warp-uniform)
    if (g_flags[bt]) return;             // visible -> GEMM writes it
    const int d4 = j & 127;
    const int t  = bt % P2T;
    const float4 m = mt4[d4];
    const float4 p = pos4[t * 128 + d4];
    const float4 v = ((const float4*)(ve + (t >= PT ? PDEC : 0)))[d4];
    out4[j] = make_float4(m.x + p.x + v.x, m.y + p.y + v.y,
                          m.z + p.z + v.z, m.w + p.w + v.w);
}

// ===========================================================================
// Kernel 3: fp16 mma.sync GEMM (12544 x 512 x 1024) + fused scatter epilogue
//   BM=128, BN=128, BK=64, SW128 swizzle, 3-stage cp.async pipeline,
//   one __syncthreads per k-tile, 2 CTAs/SM (launch_bounds 256,2).
// ===========================================================================
__device__ __forceinline__ void cp_async16(void* smem, const void* gmem) {
    uint32_t s = (uint32_t)__cvta_generic_to_shared(smem);
    asm volatile("cp.async.cg.shared.global [%0], [%1], 16;\n" :: "r"(s), "l"(gmem));
}
__device__ __forceinline__ void cp_commit() {
    asm volatile("cp.async.commit_group;\n" ::: "memory");
}
template<int N> __device__ __forceinline__ void cp_wait() {
    asm volatile("cp.async.wait_group %0;\n" :: "n"(N) : "memory");
}
__device__ __forceinline__ void ldsm_x4(uint32_t& r0, uint32_t& r1,
                                        uint32_t& r2, uint32_t& r3, uint32_t addr) {
    asm volatile("ldmatrix.sync.aligned.m8n8.x4.shared.b16 {%0,%1,%2,%3}, [%4];"
                 : "=r"(r0), "=r"(r1), "=r"(r2), "=r"(r3) : "r"(addr));
}
__device__ __forceinline__ void mma_f16(float* c, const uint32_t* a, const uint32_t* b) {
    asm volatile(
        "mma.sync.aligned.m16n8k16.row.col.f32.f16.f16.f32 "
        "{%0,%1,%2,%3},{%4,%5,%6,%7},{%8,%9},{%0,%1,%2,%3};\n"
        : "+f"(c[0]), "+f"(c[1]), "+f"(c[2]), "+f"(c[3])
        : "r"(a[0]), "r"(a[1]), "r"(a[2]), "r"(a[3]), "r"(b[0]), "r"(b[1]));
}
#define SWZ(off) ((off) ^ (((off) >> 3) & 0x70))

#define TILE_B    16384                    // 128 rows x 128 bytes
#define NSTAGE    3
#define GEMM_SMEM (2 * NSTAGE * TILE_B)    // 96 KB

__global__ __launch_bounds__(256, 2)
void gemm_hmma_kernel(const float* __restrict__ bias,
                      const float* __restrict__ pos,
                      const float* __restrict__ ve,
                      float* __restrict__ out) {
    extern __shared__ char smem[];
    char* As = smem;                       // 3 stages x 16 KB
    char* Bs = smem + NSTAGE * TILE_B;     // 3 stages x 16 KB

    const int tid  = threadIdx.x;
    const int warp = tid >> 5, lane = tid & 31;
    const int g    = lane >> 2;
    const int tig  = lane & 3;
    const int wm   = warp >> 2;            // 0..1
    const int wn   = warp & 3;             // 0..3
    const int bn0  = blockIdx.x * 128, bm0 = blockIdx.y * 128;

    // per-thread load slots: 4 x 16B units per matrix per stage
    int ld_soff[4];
    const __half* ld_xa[4];
    const __half* ld_wb[4];
    #pragma unroll
    for (int i = 0; i < 4; i++) {
        const int idx16 = tid + i * 256;
        const int row = idx16 >> 3, c16 = idx16 & 7;
        ld_soff[i] = SWZ(row * 128 + c16 * 16);
        ld_xa[i]   = g_xh + (size_t)(bm0 + row) * PENC + c16 * 8;
        ld_wb[i]   = g_wh + (size_t)(bn0 + row) * PENC + c16 * 8;
    }
    auto issue = [&](int kt, int buf) {
        const int kc0 = kt * 64;
        #pragma unroll
        for (int i = 0; i < 4; i++) {
            cp_async16(As + buf * TILE_B + ld_soff[i], ld_xa[i] + kc0);
            cp_async16(Bs + buf * TILE_B + ld_soff[i], ld_wb[i] + kc0);
        }
    };

    float acc[4][4][4];
    #pragma unroll
    for (int mi = 0; mi < 4; mi++)
        #pragma unroll
        for (int ni = 0; ni < 4; ni++)
            #pragma unroll
            for (int ci = 0; ci < 4; ci++) acc[mi][ni][ci] = 0.f;

    const int a_row = (lane & 15);
    const int a_chk = (lane >> 4);
    const int b_row = ((lane >> 4) * 8) + (lane & 7);
    const int b_chk = ((lane >> 3) & 1);

    issue(0, 0); cp_commit();
    issue(1, 1); cp_commit();

    const int KT = PENC / 64;              // 16
    for (int kt = 0; kt < KT; kt++) {
        cp_wait<1>();                      // stage kt landed
        __syncthreads();                   // all warps done with stage kt-1 too
        if (kt + 2 < KT) { issue(kt + 2, (kt + 2) % NSTAGE); cp_commit(); }

        const int st = kt % NSTAGE;
        const uint32_t sA = (uint32_t)__cvta_generic_to_shared(As + st * TILE_B);
        const uint32_t sB = (uint32_t)__cvta_generic_to_shared(Bs + st * TILE_B);

        #pragma unroll
        for (int ks = 0; ks < 4; ks++) {
            uint32_t af[4][4], bf[4][2];
            #pragma unroll
            for (int mi = 0; mi < 4; mi++) {
                const int r = wm * 64 + mi * 16 + a_row;
                const int c = (ks * 2 + a_chk) ^ (r & 7);
                ldsm_x4(af[mi][0], af[mi][1], af[mi][2], af[mi][3],
                        sA + r * 128 + c * 16);
            }
            #pragma unroll
            for (int nj = 0; nj < 2; nj++) {
                const int r = wn * 32 + nj * 16 + b_row;
                const int c = (ks * 2 + b_chk) ^ (r & 7);
                ldsm_x4(bf[2*nj][0], bf[2*nj][1], bf[2*nj+1][0], bf[2*nj+1][1],
                        sB + r * 128 + c * 16);
            }
            #pragma unroll
            for (int mi = 0; mi < 4; mi++)
                #pragma unroll
                for (int ni = 0; ni < 4; ni++)
                    mma_f16(acc[mi][ni], af[mi], bf[ni]);
        }
    }

    // -------- fused scatter epilogue --------
    #pragma unroll
    for (int mi = 0; mi < 4; mi++) {
        #pragma unroll
        for (int h = 0; h < 2; h++) {
            const int r  = bm0 + wm * 64 + mi * 16 + g + h * 8;
            const int bb = r / PV;
            const int v  = r - bb * PV;
            const int t  = g_vis[bb * PV + v];
            const float* posrow = pos + (size_t)t * PDEC;
            const float* verow  = ve + (t >= PT ? PDEC : 0);
            float* outrow = out + ((size_t)bb * P2T + t) * PDEC;
            #pragma unroll
            for (int ni = 0; ni < 4; ni++) {
                const int n = bn0 + wn * 32 + ni * 8 + 2 * tig;
                float o0 = acc[mi][ni][2 * h + 0] + bias[n]     + posrow[n]     + verow[n];
                float o1 = acc[mi][ni][2 * h + 1] + bias[n + 1] + posrow[n + 1] + verow[n + 1];
                *(float2*)(outrow + n) = make_float2(o0, o1);
            }
        }
    }
}

// ===========================================================================
// launch
// ===========================================================================
extern "C" void kernel_launch(void* const* d_in, const int* in_sizes, int n_in,
                              void* d_out, int out_size) {
    const float* x    = (const float*)d_in[0];  // (B, V, ENC)
    const void*  mids = d_in[1];                // (B, M) int64 or int32
    const float* W    = (const float*)d_in[2];  // (DEC, ENC)
    const float* bias = (const float*)d_in[3];  // (DEC)
    const float* mt   = (const float*)d_in[4];  // (1,1,DEC)
    const float* pos  = (const float*)d_in[5];  // (1, 2T, DEC)
    const float* ve   = (const float*)d_in[6];  // (2, DEC)
    float* out = (float*)d_out;                 // (B, 2T, DEC)

    cudaFuncSetAttribute(gemm_hmma_kernel,
                         cudaFuncAttributeMaxDynamicSharedMemorySize, GEMM_SMEM);

    vis_ids_kernel<<<PB, 128>>>(mids);

    prep_kernel<<<(NALL4 + 255) / 256, 256>>>((const float4*)x, (const float4*)W,
                                              (const float4*)mt, (const float4*)pos,
                                              ve, (float4*)out);

    dim3 grid(PDEC / 128, MROWS / 128);         // (4, 98)
    gemm_hmma_kernel<<<grid, 256, GEMM_SMEM>>>(bias, pos, ve, out);

    (void)in_sizes; (void)n_in; (void)out_size;
}

// round 15
// speedup vs baseline: 1.6943x; 1.0192x over previous
#include <cuda_runtime.h>
#include <cuda_fp16.h>
#include <cuda_bf16.h>
#include <cstdint>

// ---------------- problem constants ----------------
#define PB    128
#define PT    196
#define P2T   392
#define PENC  1024
#define PDEC  512
#define PV    98
#define PM    294
#define MROWS (PB*PV)          // 12544

// ---------------- device scratch ----------------
__device__ int            g_vis[MROWS];
__device__ unsigned char  g_flags[PB * P2T];                       // 1 = visible
__device__ __align__(16) __half g_xh[(size_t)MROWS * PENC];        // 25.7 MB
__device__ __align__(16) __half g_wh[(size_t)PDEC  * PENC];        // 1 MB

#define NX4   (MROWS * PENC / 4)          // 3,211,264
#define NW4   (PDEC * PENC / 4)           //   131,072
#define NCVT4 (NX4 + NW4)                 // 3,342,336 (= 13056 * 256 exactly)
#define NF4   (PB * P2T * (PDEC / 4))     // 6,422,528 (= 784 * 8192 exactly)
#define VISBLK 128

// ===========================================================================
// Kernel 1 (prep): blocks 0..127 = visible-id scan; rest = fp32->fp16 convert
// ===========================================================================
__global__ void prep_kernel(const float4* __restrict__ x4,
                            const float4* __restrict__ w4,
                            const void*   __restrict__ mids_raw) {
    const int tid = threadIdx.x;                      // 256 threads

    if (blockIdx.x >= VISBLK) {
        // ---- convert part (grid sized exactly: no bounds check) ----
        const int i = (blockIdx.x - VISBLK) * 256 + tid;
        float4 v; __half* dst;
        if (i < NX4) { v = x4[i];       dst = g_xh + (size_t)i * 4; }
        else         { v = w4[i - NX4]; dst = g_wh + (size_t)(i - NX4) * 4; }
        __half2 h0 = __floats2half2_rn(v.x, v.y);
        __half2 h1 = __floats2half2_rn(v.z, v.w);
        uint2 p; p.x = *(const uint32_t*)&h0; p.y = *(const uint32_t*)&h1;
        *(uint2*)dst = p;
        return;
    }

    // ---- visible ids for batch row b (256 threads) ----
    __shared__ unsigned char flags[512];
    __shared__ int warp_sum[8];
    __shared__ int is64s;
    const int b = blockIdx.x;
    const int lane = tid & 31, wid = tid >> 5;

    if (tid == 0) is64s = 1;
    flags[tid]       = (tid < P2T) ? 1 : 0;
    flags[tid + 256] = (tid + 256 < P2T) ? 1 : 0;
    __syncthreads();
    {   // int64 vs int32 detection on row 0 (racy 0-write is fine)
        const long long* p = (const long long*)mids_raw;
        for (int i = tid; i < PM; i += 256) {
            long long v = p[i];
            if (v < 0 || v >= P2T) is64s = 0;
        }
    }
    __syncthreads();
    if (is64s) {
        const long long* m = ((const long long*)mids_raw) + (size_t)b * PM;
        for (int i = tid; i < PM; i += 256) flags[(int)m[i]] = 0;
    } else {
        const int* m = ((const int*)mids_raw) + (size_t)b * PM;
        for (int i = tid; i < PM; i += 256) flags[m[i]] = 0;
    }
    __syncthreads();

    const int f0 = flags[2 * tid], f1 = flags[2 * tid + 1];
    const int local = f0 + f1;
    int s = local;
    #pragma unroll
    for (int off = 1; off < 32; off <<= 1) {
        int n = __shfl_up_sync(0xffffffffu, s, off);
        if (lane >= off) s += n;
    }
    if (lane == 31) warp_sum[wid] = s;
    __syncthreads();
    int base = 0;
    #pragma unroll
    for (int w = 0; w < 8; w++) if (w < wid) base += warp_sum[w];
    int c = base + s - local;
    if (f0) g_vis[b * PV + (c++)] = 2 * tid;
    if (f1) g_vis[b * PV + c]     = 2 * tid + 1;
    for (int i = tid; i < P2T; i += 256) g_flags[b * P2T + i] = flags[i];
}

// ===========================================================================
// Kernel 2: fp16 HMMA GEMM (12544 x 512 x 1024) + masked fill + scatter epi
//   BM=128, BN=64, BK=64, warp tile 32x32 (8 warps = 4m x 2n), SW128,
//   3-stage cp.async, 3 CTAs/SM. Fill: 2x256 float4 per k-iter (flag-gated).
// ===========================================================================
__device__ __forceinline__ void cp_async16(void* smem, const void* gmem) {
    uint32_t s = (uint32_t)__cvta_generic_to_shared(smem);
    asm volatile("cp.async.cg.shared.global [%0], [%1], 16;\n" :: "r"(s), "l"(gmem));
}
__device__ __forceinline__ void cp_commit() {
    asm volatile("cp.async.commit_group;\n" ::: "memory");
}
template<int N> __device__ __forceinline__ void cp_wait() {
    asm volatile("cp.async.wait_group %0;\n" :: "n"(N) : "memory");
}
__device__ __forceinline__ void ldsm_x4(uint32_t& r0, uint32_t& r1,
                                        uint32_t& r2, uint32_t& r3, uint32_t addr) {
    asm volatile("ldmatrix.sync.aligned.m8n8.x4.shared.b16 {%0,%1,%2,%3}, [%4];"
                 : "=r"(r0), "=r"(r1), "=r"(r2), "=r"(r3) : "r"(addr));
}
__device__ __forceinline__ void mma_f16(float* c, const uint32_t* a, const uint32_t* b) {
    asm volatile(
        "mma.sync.aligned.m16n8k16.row.col.f32.f16.f16.f32 "
        "{%0,%1,%2,%3},{%4,%5,%6,%7},{%8,%9},{%0,%1,%2,%3};\n"
        : "+f"(c[0]), "+f"(c[1]), "+f"(c[2]), "+f"(c[3])
        : "r"(a[0]), "r"(a[1]), "r"(a[2]), "r"(a[3]), "r"(b[0]), "r"(b[1]));
}
#define SWZ(off) ((off) ^ (((off) >> 3) & 0x70))

#define TILE_A    16384                    // 128 rows x 128 B
#define TILE_BB   8192                     //  64 rows x 128 B
#define NSTAGE    3
#define GEMM_SMEM (NSTAGE * (TILE_A + TILE_BB))   // 73728 B = 72 KB

__global__ __launch_bounds__(256, 3)
void gemm_hmma_kernel(const float* __restrict__ bias,
                      const float* __restrict__ pos,
                      const float* __restrict__ ve,
                      const float4* __restrict__ mt4,
                      float* __restrict__ out) {
    extern __shared__ char smem[];
    char* As = smem;                          // 3 x 16 KB
    char* Bs = smem + NSTAGE * TILE_A;        // 3 x  8 KB

    const int tid  = threadIdx.x;
    const int warp = tid >> 5, lane = tid & 31;
    const int g    = lane >> 2;
    const int tig  = lane & 3;
    const int wm   = warp & 3;                // 0..3  (m position, x32)
    const int wn   = warp >> 2;               // 0..1  (n position, x32)
    const int bn0  = blockIdx.x * 64, bm0 = blockIdx.y * 128;
    const int cta  = blockIdx.y * 8 + blockIdx.x;     // 0..783
    const int fill0 = cta * 8192;                     // float4 index base

    const float4* pos4 = (const float4*)pos;
    float4* out4 = (float4*)out;

    // per-thread cp.async slots: A 4 x 16B, B 2 x 16B per stage
    int a_soff[4]; const __half* a_g[4];
    int b_soff[2]; const __half* b_g[2];
    #pragma unroll
    for (int i = 0; i < 4; i++) {
        const int idx16 = tid + i * 256;
        const int row = idx16 >> 3, c16 = idx16 & 7;
        a_soff[i] = SWZ(row * 128 + c16 * 16);
        a_g[i]    = g_xh + (size_t)(bm0 + row) * PENC + c16 * 8;
    }
    #pragma unroll
    for (int i = 0; i < 2; i++) {
        const int idx16 = tid + i * 256;
        const int row = idx16 >> 3, c16 = idx16 & 7;  // row 0..63
        b_soff[i] = SWZ(row * 128 + c16 * 16);
        b_g[i]    = g_wh + (size_t)(bn0 + row) * PENC + c16 * 8;
    }
    auto issue = [&](int kt, int buf) {
        const int kc0 = kt * 64;
        #pragma unroll
        for (int i = 0; i < 4; i++)
            cp_async16(As + buf * TILE_A + a_soff[i], a_g[i] + kc0);
        #pragma unroll
        for (int i = 0; i < 2; i++)
            cp_async16(Bs + buf * TILE_BB + b_soff[i], b_g[i] + kc0);
    };

    float acc[2][4][4];
    #pragma unroll
    for (int mi = 0; mi < 2; mi++)
        #pragma unroll
        for (int ni = 0; ni < 4; ni++)
            #pragma unroll
            for (int ci = 0; ci < 4; ci++) acc[mi][ni][ci] = 0.f;

    const int a_row = (lane & 15);
    const int a_chk = (lane >> 4);
    const int b_row = ((lane >> 4) * 8) + (lane & 7);
    const int b_chk = ((lane >> 3) & 1);

    issue(0, 0); cp_commit();
    issue(1, 1); cp_commit();

    const int KT = PENC / 64;                 // 16
    for (int kt = 0; kt < KT; kt++) {
        if (kt + 1 < KT) cp_wait<1>();        // stage kt landed
        else             cp_wait<0>();        // last stage: full drain (no race)
        __syncthreads();
        if (kt + 2 < KT) { issue(kt + 2, (kt + 2) % NSTAGE); cp_commit(); }

        // ---- interleaved masked fill: 2 x 256 float4 (flag-gated, disjoint
        //      from epilogue's visible rows -> no race) ----
        #pragma unroll
        for (int u = 0; u < 2; u++) {
            const int j  = fill0 + (kt * 2 + u) * 256 + tid;
            const int bt = j >> 7;            // warp-uniform
            if (!g_flags[bt]) {
                const int d4 = j & 127;
                const int t  = bt % P2T;
                const float4 m = mt4[d4];
                const float4 p = pos4[t * 128 + d4];
                const float4 vv = *(const float4*)(ve + (t >= PT ? PDEC : 0) + d4 * 4);
                out4[j] = make_float4(m.x + p.x + vv.x, m.y + p.y + vv.y,
                                      m.z + p.z + vv.z, m.w + p.w + vv.w);
            }
        }

        const int st = kt % NSTAGE;
        const uint32_t sA = (uint32_t)__cvta_generic_to_shared(As + st * TILE_A);
        const uint32_t sB = (uint32_t)__cvta_generic_to_shared(Bs + st * TILE_BB);

        #pragma unroll
        for (int ks = 0; ks < 4; ks++) {
            uint32_t af[2][4], bf[4][2];
            #pragma unroll
            for (int mi = 0; mi < 2; mi++) {
                const int r = wm * 32 + mi * 16 + a_row;
                const int c = (ks * 2 + a_chk) ^ (r & 7);
                ldsm_x4(af[mi][0], af[mi][1], af[mi][2], af[mi][3],
                        sA + r * 128 + c * 16);
            }
            #pragma unroll
            for (int nj = 0; nj < 2; nj++) {
                const int r = wn * 32 + nj * 16 + b_row;
                const int c = (ks * 2 + b_chk) ^ (r & 7);
                ldsm_x4(bf[2*nj][0], bf[2*nj][1], bf[2*nj+1][0], bf[2*nj+1][1],
                        sB + r * 128 + c * 16);
            }
            #pragma unroll
            for (int mi = 0; mi < 2; mi++)
                #pragma unroll
                for (int ni = 0; ni < 4; ni++)
                    mma_f16(acc[mi][ni], af[mi], bf[ni]);
        }
    }

    // -------- fused scatter epilogue (visible tokens) --------
    #pragma unroll
    for (int mi = 0; mi < 2; mi++) {
        #pragma unroll
        for (int h = 0; h < 2; h++) {
            const int r  = bm0 + wm * 32 + mi * 16 + g + h * 8;   // GEMM row
            const int bb = r / PV;
            const int v  = r - bb * PV;
            const int t  = g_vis[bb * PV + v];
            const float* posrow = pos + (size_t)t * PDEC;
            const float* verow  = ve + (t >= PT ? PDEC : 0);
            float* outrow = out + ((size_t)bb * P2T + t) * PDEC;
            #pragma unroll
            for (int ni = 0; ni < 4; ni++) {
                const int n = bn0 + wn * 32 + ni * 8 + 2 * tig;
                const float2 bs = *(const float2*)(bias   + n);
                const float2 ps = *(const float2*)(posrow + n);
                const float2 vs = *(const float2*)(verow  + n);
                float o0 = acc[mi][ni][2 * h + 0] + bs.x + ps.x + vs.x;
                float o1 = acc[mi][ni][2 * h + 1] + bs.y + ps.y + vs.y;
                *(float2*)(outrow + n) = make_float2(o0, o1);
            }
        }
    }
}

// ===========================================================================
// launch
// ===========================================================================
extern "C" void kernel_launch(void* const* d_in, const int* in_sizes, int n_in,
                              void* d_out, int out_size) {
    const float* x    = (const float*)d_in[0];  // (B, V, ENC)
    const void*  mids = d_in[1];                // (B, M) int64 or int32
    const float* W    = (const float*)d_in[2];  // (DEC, ENC)
    const float* bias = (const float*)d_in[3];  // (DEC)
    const float* mt   = (const float*)d_in[4];  // (1,1,DEC)
    const float* pos  = (const float*)d_in[5];  // (1, 2T, DEC)
    const float* ve   = (const float*)d_in[6];  // (2, DEC)
    float* out = (float*)d_out;                 // (B, 2T, DEC)

    cudaFuncSetAttribute(gemm_hmma_kernel,
                         cudaFuncAttributeMaxDynamicSharedMemorySize, GEMM_SMEM);

    // 1) vis-ids + fp32->fp16 convert (one launch)
    prep_kernel<<<VISBLK + NCVT4 / 256, 256>>>((const float4*)x, (const float4*)W, mids);

    // 2) GEMM + masked fill + visible scatter (one launch)
    dim3 grid(PDEC / 64, MROWS / 128);          // (8, 98) = 784 CTAs
    gemm_hmma_kernel<<<grid, 256, GEMM_SMEM>>>(bias, pos, ve, (const float4*)mt, out);

    (void)in_sizes; (void)n_in; (void)out_size;
}